// round 9
// baseline (speedup 1.0000x reference)
#include <cuda_runtime.h>

#define TT 2048
#define NB 512
#define FULLM 0xFFFFFFFFu
typedef unsigned long long ull;

__device__ __forceinline__ float tanhap(float x) {
    float r; asm("tanh.approx.f32 %0, %1;" : "=f"(r) : "f"(x)); return r;
}
__device__ __forceinline__ ull pk(float lo, float hi) {
    ull r; asm("mov.b64 %0, {%1, %2};" : "=l"(r) : "f"(lo), "f"(hi)); return r;
}
__device__ __forceinline__ void upk(ull v, float& lo, float& hi) {
    asm("mov.b64 {%0, %1}, %2;" : "=f"(lo), "=f"(hi) : "l"(v));
}
__device__ __forceinline__ ull fma2(ull a, ull b, ull c) {
    ull d; asm("fma.rn.f32x2 %0, %1, %2, %3;" : "=l"(d) : "l"(a), "l"(b), "l"(c)); return d;
}
__device__ __forceinline__ ull add2(ull a, ull b) {
    ull d; asm("add.rn.f32x2 %0, %1, %2;" : "=l"(d) : "l"(a), "l"(b)); return d;
}
__device__ __forceinline__ ull d2l(double d) { return (ull)__double_as_longlong(d); }

__device__ __forceinline__ void cp_async4(void* smem_dst, const void* gmem_src) {
    unsigned saddr = (unsigned)__cvta_generic_to_shared(smem_dst);
    asm volatile("cp.async.ca.shared.global [%0], [%1], 4;\n"
                 :: "r"(saddr), "l"(gmem_src) : "memory");
}
__device__ __forceinline__ void cp_commit() {
    asm volatile("cp.async.commit_group;\n" ::: "memory");
}
__device__ __forceinline__ void cp_wait1() {
    asm volatile("cp.async.wait_group 1;\n" ::: "memory");
}

// Ordered h-row access (asm + memory clobber pins program order; same-warp
// shared ops retire in order through the LSU).
__device__ __forceinline__ void sts_h(unsigned addr, float v) {
    asm volatile("st.shared.f32 [%0], %1;" :: "r"(addr), "f"(v) : "memory");
}
__device__ __forceinline__ void lds_hpairs(unsigned a, ull* p) {
    asm volatile("ld.shared.v2.u64 {%0, %1}, [%2];"
                 : "=l"(p[0]), "=l"(p[1]) : "r"(a) : "memory");
    asm volatile("ld.shared.v2.u64 {%0, %1}, [%2+16];"
                 : "=l"(p[2]), "=l"(p[3]) : "r"(a) : "memory");
    asm volatile("ld.shared.v2.u64 {%0, %1}, [%2+32];"
                 : "=l"(p[4]), "=l"(p[5]) : "r"(a) : "memory");
    asm volatile("ld.shared.b64 %0, [%1+48];"
                 : "=l"(p[6]) : "r"(a) : "memory");
}
__device__ __forceinline__ void ldx(const float* row, ull* p) {
    const double2* r = reinterpret_cast<const double2*>(row);
    const double2 q0 = r[0], q1 = r[1], q2 = r[2];
    const double  q3 = *reinterpret_cast<const double*>(row + 12);
    p[0] = d2l(q0.x); p[1] = d2l(q0.y); p[2] = d2l(q1.x); p[3] = d2l(q1.y);
    p[4] = d2l(q2.x); p[5] = d2l(q2.y); p[6] = d2l(q3);
}

__global__ void __launch_bounds__(32)
lstm_dual(const float* __restrict__ x,
          const float* __restrict__ W_ih,
          const float* __restrict__ W_hh,
          const float* __restrict__ b_ih,
          const float* __restrict__ b_hh,
          const float* __restrict__ fc_w,
          const float* __restrict__ fc_b,
          float* __restrict__ out)
{
    // Two sequences per warp: two 16-deep x rings + two double-buffered h rows.
    __shared__ __align__(16) float xrA[16][16];
    __shared__ __align__(16) float xrB[16][16];
    __shared__ __align__(16) float hbA[2][16];
    __shared__ __align__(16) float hbB[2][16];

    const int lane = threadIdx.x & 31;
    const int s0 = blockIdx.x * 2;
    const float* xb0 = x + (size_t)s0 * TT * 13;
    const float* xb1 = x + (size_t)(s0 + 1) * TT * 13;
    float* ob0 = out + (size_t)s0 * TT;
    float* ob1 = out + (size_t)(s0 + 1) * TT;

    const unsigned haA = (unsigned)__cvta_generic_to_shared(&hbA[0][0]);
    const unsigned haB = (unsigned)__cvta_generic_to_shared(&hbB[0][0]);

    // Zero rings + h buffers once (cp.async only writes [0..12]).
    #pragma unroll
    for (int i = 0; i < 8; i++) {
        reinterpret_cast<float*>(xrA)[i * 32 + lane] = 0.0f;
        reinterpret_cast<float*>(xrB)[i * 32 + lane] = 0.0f;
    }
    if (lane < 16) {
        hbA[0][lane] = 0.0f; hbA[1][lane] = 0.0f;
        hbB[0][lane] = 0.0f; hbB[1][lane] = 0.0f;
    }

    // Gate map (shared weights for both sequences):
    // lane L<26: A = gate L (sigmoid: i for L<13, f else), B = gate 26+L
    // (g=tanh for L<13, o=sigmoid else). Lane 26: B-dot = FC head.
    float wiA[13], whAs[13], wiB[13], whBs[13];
    float biasA = 0.0f, biasB = 0.0f;
    {
        const bool g26 = (lane < 26);
        const float sA = 0.5f;
        const float sB = (lane < 13) ? 1.0f : 0.5f;
        const int rA = g26 ? lane : 0;
        const int rB = g26 ? lane + 26 : 0;
        #pragma unroll
        for (int k = 0; k < 13; k++) {
            wiA[k]  = g26 ? sA * W_ih[rA * 13 + k] : 0.0f;
            whAs[k] = g26 ? sA * W_hh[rA * 13 + k] : 0.0f;
            wiB[k]  = g26 ? sB * W_ih[rB * 13 + k] : 0.0f;
            whBs[k] = g26 ? sB * W_hh[rB * 13 + k] : 0.0f;
        }
        if (g26) {
            biasA = sA * (b_ih[rA] + b_hh[rA]);
            biasB = sB * (b_ih[rB] + b_hh[rB]);
        }
        if (lane == 26) {
            #pragma unroll
            for (int k = 0; k < 13; k++) { wiB[k] = 0.0f; whBs[k] = 0.5f * fc_w[k]; }
            biasB = 0.5f * fc_b[0];
        }
    }

    ull wxA[7], whA[7], wxB[7], whB[7];
    #pragma unroll
    for (int p = 0; p < 6; p++) {
        wxA[p] = pk(wiA[2*p],  wiA[2*p+1]);
        whA[p] = pk(whAs[2*p], whAs[2*p+1]);
        wxB[p] = pk(wiB[2*p],  wiB[2*p+1]);
        whB[p] = pk(whBs[2*p], whBs[2*p+1]);
    }
    wxA[6] = pk(wiA[12],  0.0f);
    whA[6] = pk(whAs[12], 0.0f);
    wxB[6] = pk(wiB[12],  0.0f);
    whB[6] = pk(whBs[12], 0.0f);

    const ull biasPA = pk(biasA, 0.0f);
    const ull biasPB = pk(biasB, 0.0f);
    const ull z64    = pk(0.0f, 0.0f);

    const float mB = (lane < 13) ? 1.0f : 0.5f;
    const float aB = (lane < 13) ? 0.0f : 0.5f;

    float h0 = 0.0f, c0 = 0.0f, h1 = 0.0f, c1 = 0.0f;

    // x fetch ownership: lane<13 -> seq0 element `lane`; 16<=lane<29 -> seq1
    // element `lane-16`.
    const int kx = (lane < 13) ? lane : lane - 16;
    const bool fA = (lane < 13);
    const bool fB = (lane >= 16 && lane < 29);

    // Prologue: rows 0..7 of both sequences as ONE commit group.
    #pragma unroll
    for (int r = 0; r < 8; r++) {
        if (fA) cp_async4(&xrA[r][kx], xb0 + r * 13 + kx);
        if (fB) cp_async4(&xrB[r][kx], xb1 + r * 13 + kx);
    }
    cp_commit();

// One dual-sequence step: advances BOTH sequences by one timestep.
#define GATES(pre_A, pre_B, xp, hp)                                            \
    ull xa0 = fma2(xp[0], wxA[0], biasPA);                                     \
    ull xa1 = fma2(xp[1], wxA[1], z64);                                        \
    xa0 = fma2(xp[2], wxA[2], xa0);                                            \
    xa1 = fma2(xp[3], wxA[3], xa1);                                            \
    xa0 = fma2(xp[4], wxA[4], xa0);                                            \
    xa1 = fma2(xp[5], wxA[5], xa1);                                            \
    xa0 = fma2(xp[6], wxA[6], xa0);                                            \
    ull ha0 = fma2(hp[0], whA[0], z64);                                        \
    ull ha1 = fma2(hp[1], whA[1], z64);                                        \
    ha0 = fma2(hp[2], whA[2], ha0);                                            \
    ha1 = fma2(hp[3], whA[3], ha1);                                            \
    ha0 = fma2(hp[4], whA[4], ha0);                                            \
    ha1 = fma2(hp[5], whA[5], ha1);                                            \
    ha0 = fma2(hp[6], whA[6], ha0);                                            \
    ull xb0_ = fma2(xp[0], wxB[0], biasPB);                                    \
    ull xb1_ = fma2(xp[1], wxB[1], z64);                                       \
    xb0_ = fma2(xp[2], wxB[2], xb0_);                                          \
    xb1_ = fma2(xp[3], wxB[3], xb1_);                                          \
    xb0_ = fma2(xp[4], wxB[4], xb0_);                                          \
    xb1_ = fma2(xp[5], wxB[5], xb1_);                                          \
    xb0_ = fma2(xp[6], wxB[6], xb0_);                                          \
    ull hb0_ = fma2(hp[0], whB[0], z64);                                       \
    ull hb1_ = fma2(hp[1], whB[1], z64);                                       \
    hb0_ = fma2(hp[2], whB[2], hb0_);                                          \
    hb1_ = fma2(hp[3], whB[3], hb1_);                                          \
    hb0_ = fma2(hp[4], whB[4], hb0_);                                          \
    hb1_ = fma2(hp[5], whB[5], hb1_);                                          \
    hb0_ = fma2(hp[6], whB[6], hb0_);                                          \
    ull sA_ = add2(add2(xa0, xa1), add2(ha0, ha1));                            \
    ull sB_ = add2(add2(xb0_, xb1_), add2(hb0_, hb1_));                        \
    float pa0, pa1, pb0, pb1;                                                  \
    upk(sA_, pa0, pa1); upk(sB_, pb0, pb1);                                    \
    pre_A = pa0 + pa1;                                                         \
    pre_B = pb0 + pb1;

#define STEP(SLOT, RB, WB, TTC) do {                                           \
    ull hpA[7], hpB[7];                                                        \
    lds_hpairs(haA + (RB) * 64, hpA);                                          \
    lds_hpairs(haB + (RB) * 64, hpB);                                          \
    ull xpA[7], xpB[7];                                                        \
    ldx(&xrA[(SLOT)][0], xpA);                                                 \
    ldx(&xrB[(SLOT)][0], xpB);                                                 \
    float preA0, preB0, preA1, preB1;                                          \
    { GATES(preA0, preB0, xpA, hpA) }                                          \
    { GATES(preA1, preB1, xpB, hpB) }                                          \
    const float actA0 = fmaf(0.5f, tanhap(preA0), 0.5f);                       \
    const float actB0 = fmaf(mB,   tanhap(preB0), aB);                         \
    const float actA1 = fmaf(0.5f, tanhap(preA1), 0.5f);                       \
    const float actB1 = fmaf(mB,   tanhap(preB1), aB);                         \
    if (lane == 26 && (TTC) > 0) {                                             \
        ob0[(TTC) - 1] = actB0;                                                \
        ob1[(TTC) - 1] = actB1;                                                \
    }                                                                          \
    const float fg0 = __shfl_sync(FULLM, actA0, (lane + 13) & 31);             \
    const float og0 = __shfl_sync(FULLM, actB0, (lane + 13) & 31);             \
    const float fg1 = __shfl_sync(FULLM, actA1, (lane + 13) & 31);             \
    const float og1 = __shfl_sync(FULLM, actB1, (lane + 13) & 31);             \
    c0 = fmaf(fg0, c0, actA0 * actB0);                                         \
    c1 = fmaf(fg1, c1, actA1 * actB1);                                         \
    h0 = og0 * tanhap(c0);                                                     \
    h1 = og1 * tanhap(c1);                                                     \
    if (lane < 13) {                                                           \
        sts_h(haA + (WB) * 64 + lane * 4, h0);                                 \
        sts_h(haB + (WB) * 64 + lane * 4, h1);                                 \
    }                                                                          \
} while (0)

    for (int t = 0; t < TT; t += 16) {
        // Half 0: prefetch rows t+8..t+15 into slots 8..15; process slots 0..7.
        #pragma unroll
        for (int r = 0; r < 8; r++) {
            if (t + 8 + r < TT) {
                if (fA) cp_async4(&xrA[8 + r][kx], xb0 + (size_t)(t + 8 + r) * 13 + kx);
                if (fB) cp_async4(&xrB[8 + r][kx], xb1 + (size_t)(t + 8 + r) * 13 + kx);
            }
        }
        cp_commit();
        cp_wait1();
        __syncwarp();
        STEP(0, 1, 0, t + 0);
        STEP(1, 0, 1, t + 1);
        STEP(2, 1, 0, t + 2);
        STEP(3, 0, 1, t + 3);
        STEP(4, 1, 0, t + 4);
        STEP(5, 0, 1, t + 5);
        STEP(6, 1, 0, t + 6);
        STEP(7, 0, 1, t + 7);

        // Half 1: prefetch rows t+16..t+23 into slots 0..7; process slots 8..15.
        #pragma unroll
        for (int r = 0; r < 8; r++) {
            if (t + 16 + r < TT) {
                if (fA) cp_async4(&xrA[r][kx], xb0 + (size_t)(t + 16 + r) * 13 + kx);
                if (fB) cp_async4(&xrB[r][kx], xb1 + (size_t)(t + 16 + r) * 13 + kx);
            }
        }
        cp_commit();
        cp_wait1();
        __syncwarp();
        STEP( 8, 1, 0, t +  8);
        STEP( 9, 0, 1, t +  9);
        STEP(10, 1, 0, t + 10);
        STEP(11, 0, 1, t + 11);
        STEP(12, 1, 0, t + 12);
        STEP(13, 0, 1, t + 13);
        STEP(14, 1, 0, t + 14);
        STEP(15, 0, 1, t + 15);
    }
#undef STEP
#undef GATES

    // Tail: final FC for both sequences. Step 2047 wrote buffer 1.
    __syncwarp();
    if (lane == 26) {
        float p0 = biasB, p1 = biasB;
        #pragma unroll
        for (int k = 0; k < 13; k++) {
            p0 = fmaf(hbA[1][k], whBs[k], p0);
            p1 = fmaf(hbB[1][k], whBs[k], p1);
        }
        ob0[TT - 1] = fmaf(0.5f, tanhap(p0), 0.5f);
        ob1[TT - 1] = fmaf(0.5f, tanhap(p1), 0.5f);
    }
}

extern "C" void kernel_launch(void* const* d_in, const int* in_sizes, int n_in,
                              void* d_out, int out_size) {
    (void)in_sizes; (void)n_in; (void)out_size;
    const float* x    = (const float*)d_in[0];
    const float* W_ih = (const float*)d_in[1];
    const float* W_hh = (const float*)d_in[2];
    const float* b_ih = (const float*)d_in[3];
    const float* b_hh = (const float*)d_in[4];
    const float* fc_w = (const float*)d_in[5];
    const float* fc_b = (const float*)d_in[6];
    float* out = (float*)d_out;

    lstm_dual<<<NB / 2, 32>>>(x, W_ih, W_hh, b_ih, b_hh, fc_w, fc_b, out);
}

// round 11
// speedup vs baseline: 1.5903x; 1.5903x over previous
#include <cuda_runtime.h>

#define TT 2048
#define NB 512
typedef unsigned long long ull;

__device__ __forceinline__ float tanhap(float x) {
    float r; asm("tanh.approx.f32 %0, %1;" : "=f"(r) : "f"(x)); return r;
}
__device__ __forceinline__ ull pk(float lo, float hi) {
    ull r; asm("mov.b64 %0, {%1, %2};" : "=l"(r) : "f"(lo), "f"(hi)); return r;
}
__device__ __forceinline__ void upk(ull v, float& lo, float& hi) {
    asm("mov.b64 {%0, %1}, %2;" : "=f"(lo), "=f"(hi) : "l"(v));
}
__device__ __forceinline__ ull fma2(ull a, ull b, ull c) {
    ull d; asm("fma.rn.f32x2 %0, %1, %2, %3;" : "=l"(d) : "l"(a), "l"(b), "l"(c)); return d;
}
__device__ __forceinline__ ull add2(ull a, ull b) {
    ull d; asm("add.rn.f32x2 %0, %1, %2;" : "=l"(d) : "l"(a), "l"(b)); return d;
}

// Ordered smem ops (asm volatile + memory clobber pins compiler order; the
// same-warp LSU retires shared accesses in order -- validated in R8).
__device__ __forceinline__ void sts_dup(unsigned addr, float v) {
    asm volatile("st.shared.v2.f32 [%0], {%1, %1};" :: "r"(addr), "f"(v) : "memory");
}
// Load 13 duplicated pairs (104 bytes) as 13 ulls.
__device__ __forceinline__ void lds13(unsigned a, ull* p) {
    asm volatile("ld.shared.v2.u64 {%0, %1}, [%2];"
                 : "=l"(p[0]), "=l"(p[1]) : "r"(a) : "memory");
    asm volatile("ld.shared.v2.u64 {%0, %1}, [%2+16];"
                 : "=l"(p[2]), "=l"(p[3]) : "r"(a) : "memory");
    asm volatile("ld.shared.v2.u64 {%0, %1}, [%2+32];"
                 : "=l"(p[4]), "=l"(p[5]) : "r"(a) : "memory");
    asm volatile("ld.shared.v2.u64 {%0, %1}, [%2+48];"
                 : "=l"(p[6]), "=l"(p[7]) : "r"(a) : "memory");
    asm volatile("ld.shared.v2.u64 {%0, %1}, [%2+64];"
                 : "=l"(p[8]), "=l"(p[9]) : "r"(a) : "memory");
    asm volatile("ld.shared.v2.u64 {%0, %1}, [%2+80];"
                 : "=l"(p[10]), "=l"(p[11]) : "r"(a) : "memory");
    asm volatile("ld.shared.b64 %0, [%1+96];"
                 : "=l"(p[12]) : "r"(a) : "memory");
}

__global__ void __launch_bounds__(32)
lstm_gpack(const float* __restrict__ x,
           const float* __restrict__ W_ih,
           const float* __restrict__ W_hh,
           const float* __restrict__ b_ih,
           const float* __restrict__ b_hh,
           const float* __restrict__ fc_w,
           const float* __restrict__ fc_b,
           float* __restrict__ out)
{
    // Duplicated-pair storage: x ring 16 rows x 32 floats (cols 0..25 used),
    // h double buffer 2 rows x 32 floats.
    __shared__ __align__(16) float xd[16][32];
    __shared__ __align__(16) float hd[2][32];

    const int lane = threadIdx.x & 31;
    const int seq  = blockIdx.x;
    const float* xb = x + (size_t)seq * TT * 13;
    float* ob = out + (size_t)seq * TT;

    const unsigned xda = (unsigned)__cvta_generic_to_shared(&xd[0][0]);
    const unsigned hda = (unsigned)__cvta_generic_to_shared(&hd[0][0]);

    // h_{-1} = 0.
    hd[0][lane] = 0.0f;
    hd[1][lane] = 0.0f;

    // Lane j<13 owns hidden unit j: pair P=(i_j, f_j), pair Q=(g_j, o_j).
    // Gate rows in W: i=j, f=13+j, g=26+j, o=39+j.
    // Sigmoid pre-scale 0.5 folded into weights; g (tanh) scale 1.
    // Lane 13: P-lo is the FC head (h-weights 0.5*fc_w, bias 0.5*fc_b).
    const bool uo = (lane < 13);
    const bool fcl = (lane == 13);
    ull wxP[13], whP[13], wxQ[13], whQ[13];
    #pragma unroll
    for (int k = 0; k < 13; k++) {
        const float xi = uo ? 0.5f * W_ih[lane * 13 + k]        : 0.0f;
        const float xf = uo ? 0.5f * W_ih[(13 + lane) * 13 + k] : 0.0f;
        const float hi = uo ? 0.5f * W_hh[lane * 13 + k]
                            : (fcl ? 0.5f * fc_w[k] : 0.0f);
        const float hf = uo ? 0.5f * W_hh[(13 + lane) * 13 + k] : 0.0f;
        const float xg = uo ? W_ih[(26 + lane) * 13 + k]        : 0.0f;
        const float xo = uo ? 0.5f * W_ih[(39 + lane) * 13 + k] : 0.0f;
        const float hg = uo ? W_hh[(26 + lane) * 13 + k]        : 0.0f;
        const float ho = uo ? 0.5f * W_hh[(39 + lane) * 13 + k] : 0.0f;
        wxP[k] = pk(xi, xf);
        whP[k] = pk(hi, hf);
        wxQ[k] = pk(xg, xo);
        whQ[k] = pk(hg, ho);
    }
    const ull biasP = pk(uo ? 0.5f * (b_ih[lane] + b_hh[lane])
                            : (fcl ? 0.5f * fc_b[0] : 0.0f),
                         uo ? 0.5f * (b_ih[13 + lane] + b_hh[13 + lane]) : 0.0f);
    const ull biasQ = pk(uo ? (b_ih[26 + lane] + b_hh[26 + lane]) : 0.0f,
                         uo ? 0.5f * (b_ih[39 + lane] + b_hh[39 + lane]) : 0.0f);
    const ull z64 = pk(0.0f, 0.0f);

    float h = 0.0f, c = 0.0f;

    // x fetch: lane<13 owns element k=lane of each row; values stored dup.
    // Prologue: rows 0..7 into smem slots 0..7; rows 8..15 into regs.
    if (lane < 13) {
        #pragma unroll
        for (int r = 0; r < 8; r++) {
            const float v = xb[r * 13 + lane];
            sts_dup(xda + r * 128 + lane * 8, v);
        }
    }
    float rf[8];
    #pragma unroll
    for (int r = 0; r < 8; r++)
        rf[r] = (lane < 13) ? xb[(8 + r) * 13 + lane] : 0.0f;

// One step. XADDR: smem addr of x row tt. FSADDR: smem addr for row tt+8
// (from rf[U]). Zero synchronization: same-warp in-order LSU + asm-volatile
// program order (R8-validated).
#define STEP(XADDR, FSADDR, U, TTC) do {                                       \
    ull hp[13];                                                                \
    lds13(hda + (RBOF(U)), hp);                                                \
    ull xp[13];                                                                \
    lds13((XADDR), xp);                                                        \
    /* publish x row tt+8 and start fetching row tt+16 */                      \
    if (lane < 13) sts_dup((FSADDR), rf[U]);                                   \
    {                                                                          \
        int row = (TTC) + 16;                                                  \
        if (row >= TT) row = TT - 1;                                           \
        rf[U] = (lane < 13) ? xb[row * 13 + lane] : 0.0f;                      \
    }                                                                          \
    /* P = (i,f): 2 x-chains + 2 h-chains, free k-reduction in SIMD halves */  \
    ull pX0 = fma2(xp[0], wxP[0], biasP);                                      \
    ull pX1 = fma2(xp[1], wxP[1], z64);                                        \
    pX0 = fma2(xp[2],  wxP[2],  pX0);                                          \
    pX1 = fma2(xp[3],  wxP[3],  pX1);                                          \
    pX0 = fma2(xp[4],  wxP[4],  pX0);                                          \
    pX1 = fma2(xp[5],  wxP[5],  pX1);                                          \
    pX0 = fma2(xp[6],  wxP[6],  pX0);                                          \
    pX1 = fma2(xp[7],  wxP[7],  pX1);                                          \
    pX0 = fma2(xp[8],  wxP[8],  pX0);                                          \
    pX1 = fma2(xp[9],  wxP[9],  pX1);                                          \
    pX0 = fma2(xp[10], wxP[10], pX0);                                          \
    pX1 = fma2(xp[11], wxP[11], pX1);                                          \
    pX0 = fma2(xp[12], wxP[12], pX0);                                          \
    ull pH0 = fma2(hp[0], whP[0], z64);                                        \
    ull pH1 = fma2(hp[1], whP[1], z64);                                        \
    pH0 = fma2(hp[2],  whP[2],  pH0);                                          \
    pH1 = fma2(hp[3],  whP[3],  pH1);                                          \
    pH0 = fma2(hp[4],  whP[4],  pH0);                                          \
    pH1 = fma2(hp[5],  whP[5],  pH1);                                          \
    pH0 = fma2(hp[6],  whP[6],  pH0);                                          \
    pH1 = fma2(hp[7],  whP[7],  pH1);                                          \
    pH0 = fma2(hp[8],  whP[8],  pH0);                                          \
    pH1 = fma2(hp[9],  whP[9],  pH1);                                          \
    pH0 = fma2(hp[10], whP[10], pH0);                                          \
    pH1 = fma2(hp[11], whP[11], pH1);                                          \
    pH0 = fma2(hp[12], whP[12], pH0);                                          \
    const ull preP = add2(add2(pX0, pX1), add2(pH0, pH1));                     \
    /* Q = (g,o) */                                                            \
    ull qX0 = fma2(xp[0], wxQ[0], biasQ);                                      \
    ull qX1 = fma2(xp[1], wxQ[1], z64);                                        \
    qX0 = fma2(xp[2],  wxQ[2],  qX0);                                          \
    qX1 = fma2(xp[3],  wxQ[3],  qX1);                                          \
    qX0 = fma2(xp[4],  wxQ[4],  qX0);                                          \
    qX1 = fma2(xp[5],  wxQ[5],  qX1);                                          \
    qX0 = fma2(xp[6],  wxQ[6],  qX0);                                          \
    qX1 = fma2(xp[7],  wxQ[7],  qX1);                                          \
    qX0 = fma2(xp[8],  wxQ[8],  qX0);                                          \
    qX1 = fma2(xp[9],  wxQ[9],  qX1);                                          \
    qX0 = fma2(xp[10], wxQ[10], qX0);                                          \
    qX1 = fma2(xp[11], wxQ[11], qX1);                                          \
    qX0 = fma2(xp[12], wxQ[12], qX0);                                          \
    ull qH0 = fma2(hp[0], whQ[0], z64);                                        \
    ull qH1 = fma2(hp[1], whQ[1], z64);                                        \
    qH0 = fma2(hp[2],  whQ[2],  qH0);                                          \
    qH1 = fma2(hp[3],  whQ[3],  qH1);                                          \
    qH0 = fma2(hp[4],  whQ[4],  qH0);                                          \
    qH1 = fma2(hp[5],  whQ[5],  qH1);                                          \
    qH0 = fma2(hp[6],  whQ[6],  qH0);                                          \
    qH1 = fma2(hp[7],  whQ[7],  qH1);                                          \
    qH0 = fma2(hp[8],  whQ[8],  qH0);                                          \
    qH1 = fma2(hp[9],  whQ[9],  qH1);                                          \
    qH0 = fma2(hp[10], whQ[10], qH0);                                          \
    qH1 = fma2(hp[11], whQ[11], qH1);                                          \
    qH0 = fma2(hp[12], whQ[12], qH0);                                          \
    const ull preQ = add2(add2(qX0, qX1), add2(qH0, qH1));                     \
    float pi, pf, pg, po;                                                      \
    upk(preP, pi, pf);                                                         \
    upk(preQ, pg, po);                                                         \
    const float ig = fmaf(0.5f, tanhap(pi), 0.5f);                             \
    const float fg = fmaf(0.5f, tanhap(pf), 0.5f);                             \
    const float gg = tanhap(pg);                                               \
    const float og = fmaf(0.5f, tanhap(po), 0.5f);                             \
    if (lane == 13 && (TTC) > 0) ob[(TTC) - 1] = ig;  /* lane13: ig==FC out */ \
    c = fmaf(fg, c, ig * gg);                                                  \
    h = og * tanhap(c);                                                        \
    if (lane < 13) sts_dup(hda + (WBOF(U)) + lane * 8, h);                     \
} while (0)

#define RBOF(U) ((((U) + 1) & 1) * 128)
#define WBOF(U) (((U) & 1) * 128)

    for (int t = 0; t < TT; t += 8) {
        // x row tt lives at slot (tt & 15). Half base offset = (t & 8) slots
        // * 128 bytes/slot = (t & 8) << 7.   [R10 bug: was << 4]
        const unsigned rb = xda + ((unsigned)(t & 8) << 7);
        const unsigned fb = xda + ((unsigned)((t + 8) & 8) << 7);
        STEP(rb + 0 * 128, fb + 0 * 128 + lane * 8, 0, t + 0);
        STEP(rb + 1 * 128, fb + 1 * 128 + lane * 8, 1, t + 1);
        STEP(rb + 2 * 128, fb + 2 * 128 + lane * 8, 2, t + 2);
        STEP(rb + 3 * 128, fb + 3 * 128 + lane * 8, 3, t + 3);
        STEP(rb + 4 * 128, fb + 4 * 128 + lane * 8, 4, t + 4);
        STEP(rb + 5 * 128, fb + 5 * 128 + lane * 8, 5, t + 5);
        STEP(rb + 6 * 128, fb + 6 * 128 + lane * 8, 6, t + 6);
        STEP(rb + 7 * 128, fb + 7 * 128 + lane * 8, 7, t + 7);
    }
#undef STEP
#undef RBOF
#undef WBOF

    // Tail: out[TT-1] = sigm(fc . h_{TT-1}); step TT-1 wrote hd row 1.
    {
        ull hp[13];
        lds13(hda + 128, hp);
        ull s0 = fma2(hp[0], whP[0], biasP);
        ull s1 = fma2(hp[1], whP[1], z64);
        #pragma unroll
        for (int k = 2; k < 13; k += 2) {
            s0 = fma2(hp[k], whP[k], s0);
            if (k + 1 < 13) s1 = fma2(hp[k + 1], whP[k + 1], s1);
        }
        const ull s = add2(s0, s1);
        float lo, hi;
        upk(s, lo, hi);
        const float v = fmaf(0.5f, tanhap(lo), 0.5f);
        if (lane == 13) ob[TT - 1] = v;
    }
}

extern "C" void kernel_launch(void* const* d_in, const int* in_sizes, int n_in,
                              void* d_out, int out_size) {
    (void)in_sizes; (void)n_in; (void)out_size;
    const float* x    = (const float*)d_in[0];
    const float* W_ih = (const float*)d_in[1];
    const float* W_hh = (const float*)d_in[2];
    const float* b_ih = (const float*)d_in[3];
    const float* b_hh = (const float*)d_in[4];
    const float* fc_w = (const float*)d_in[5];
    const float* fc_b = (const float*)d_in[6];
    float* out = (float*)d_out;

    lstm_gpack<<<NB, 32>>>(x, W_ih, W_hh, b_ih, b_hh, fc_w, fc_b, out);
}

// round 12
// speedup vs baseline: 1.8557x; 1.1669x over previous
#include <cuda_runtime.h>

#define TT 2048
#define NB 512
#define FULLM 0xFFFFFFFFu
typedef unsigned long long ull;

__device__ __forceinline__ float tanhap(float x) {
    float r; asm("tanh.approx.f32 %0, %1;" : "=f"(r) : "f"(x)); return r;
}
__device__ __forceinline__ ull pk(float lo, float hi) {
    ull r; asm("mov.b64 %0, {%1, %2};" : "=l"(r) : "f"(lo), "f"(hi)); return r;
}
__device__ __forceinline__ void upk(ull v, float& lo, float& hi) {
    asm("mov.b64 {%0, %1}, %2;" : "=f"(lo), "=f"(hi) : "l"(v));
}
__device__ __forceinline__ ull fma2(ull a, ull b, ull c) {
    ull d; asm("fma.rn.f32x2 %0, %1, %2, %3;" : "=l"(d) : "l"(a), "l"(b), "l"(c)); return d;
}
__device__ __forceinline__ ull add2(ull a, ull b) {
    ull d; asm("add.rn.f32x2 %0, %1, %2;" : "=l"(d) : "l"(a), "l"(b)); return d;
}
__device__ __forceinline__ ull d2l(double d) { return (ull)__double_as_longlong(d); }

__device__ __forceinline__ void cp_async4(void* smem_dst, const void* gmem_src) {
    unsigned saddr = (unsigned)__cvta_generic_to_shared(smem_dst);
    asm volatile("cp.async.ca.shared.global [%0], [%1], 4;\n"
                 :: "r"(saddr), "l"(gmem_src) : "memory");
}
__device__ __forceinline__ void cp_commit() {
    asm volatile("cp.async.commit_group;\n" ::: "memory");
}
__device__ __forceinline__ void cp_wait1() {
    asm volatile("cp.async.wait_group 1;\n" ::: "memory");
}

// Volatile-ordered h exchange (R8-validated: asm memory clobbers pin compiler
// order; same-warp shared ops retire in order through the LSU).
__device__ __forceinline__ void sts_h(unsigned addr, float v) {
    asm volatile("st.shared.f32 [%0], %1;" :: "r"(addr), "f"(v) : "memory");
}
__device__ __forceinline__ void lds_h(unsigned a, ull* p) {
    asm volatile("ld.shared.v2.u64 {%0, %1}, [%2];"
                 : "=l"(p[0]), "=l"(p[1]) : "r"(a) : "memory");
    asm volatile("ld.shared.v2.u64 {%0, %1}, [%2+16];"
                 : "=l"(p[2]), "=l"(p[3]) : "r"(a) : "memory");
    asm volatile("ld.shared.v2.u64 {%0, %1}, [%2+32];"
                 : "=l"(p[4]), "=l"(p[5]) : "r"(a) : "memory");
    asm volatile("ld.shared.b64 %0, [%1+48];"
                 : "=l"(p[6]) : "r"(a) : "memory");
}

__global__ void __launch_bounds__(32)
lstm_pipe(const float* __restrict__ x,
          const float* __restrict__ W_ih,
          const float* __restrict__ W_hh,
          const float* __restrict__ b_ih,
          const float* __restrict__ b_hh,
          const float* __restrict__ fc_w,
          const float* __restrict__ fc_b,
          float* __restrict__ out)
{
    // 16-deep x ring (rows padded to 16 floats, pads 0) + double-buffered h.
    __shared__ __align__(16) float xring[16][16];
    __shared__ __align__(16) float hbuf[2][16];

    const int lane = threadIdx.x & 31;
    const int seq  = blockIdx.x;
    const float* xb = x + (size_t)seq * TT * 13;
    float* ob = out + (size_t)seq * TT;

    const unsigned hda = (unsigned)__cvta_generic_to_shared(&hbuf[0][0]);

    #pragma unroll
    for (int i = 0; i < 8; i++)
        reinterpret_cast<float*>(xring)[i * 32 + lane] = 0.0f;
    if (lane < 16) { hbuf[0][lane] = 0.0f; hbuf[1][lane] = 0.0f; }

    // Lane L<26: A = gate L (sigmoid: i for L<13, f else), B = gate 26+L
    // (g=tanh for L<13, o=sigmoid else). Lane 26: B-dot = FC head.
    // Sigmoid pre-scale 0.5 folded into weights: act = m*tanh(pre)+a.
    float wiA[13], whAs[13], wiB[13], whBs[13];
    float biasA = 0.0f, biasB = 0.0f;
    {
        const bool g26 = (lane < 26);
        const float sA = 0.5f;
        const float sB = (lane < 13) ? 1.0f : 0.5f;
        const int rA = g26 ? lane : 0;
        const int rB = g26 ? lane + 26 : 0;
        #pragma unroll
        for (int k = 0; k < 13; k++) {
            wiA[k]  = g26 ? sA * W_ih[rA * 13 + k] : 0.0f;
            whAs[k] = g26 ? sA * W_hh[rA * 13 + k] : 0.0f;
            wiB[k]  = g26 ? sB * W_ih[rB * 13 + k] : 0.0f;
            whBs[k] = g26 ? sB * W_hh[rB * 13 + k] : 0.0f;
        }
        if (g26) {
            biasA = sA * (b_ih[rA] + b_hh[rA]);
            biasB = sB * (b_ih[rB] + b_hh[rB]);
        }
        if (lane == 26) {
            #pragma unroll
            for (int k = 0; k < 13; k++) { wiB[k] = 0.0f; whBs[k] = 0.5f * fc_w[k]; }
            biasB = 0.5f * fc_b[0];
        }
    }

    ull wxA[7], whA[7], wxB[7], whB[7];
    #pragma unroll
    for (int p = 0; p < 6; p++) {
        wxA[p] = pk(wiA[2*p],  wiA[2*p+1]);
        whA[p] = pk(whAs[2*p], whAs[2*p+1]);
        wxB[p] = pk(wiB[2*p],  wiB[2*p+1]);
        whB[p] = pk(whBs[2*p], whBs[2*p+1]);
    }
    wxA[6] = pk(wiA[12],  0.0f);
    whA[6] = pk(whAs[12], 0.0f);
    wxB[6] = pk(wiB[12],  0.0f);
    whB[6] = pk(whBs[12], 0.0f);

    const ull biasPA = pk(biasA, 0.0f);
    const ull biasPB = pk(biasB, 0.0f);
    const ull z64    = pk(0.0f, 0.0f);

    const float mB = (lane < 13) ? 1.0f : 0.5f;
    const float aB = (lane < 13) ? 0.0f : 0.5f;

    float h = 0.0f, c = 0.0f;
    // Pipelined x-dot accumulators for the UPCOMING step (2 chains per gate).
    ull xaA0, xaA1, xaB0, xaB1;

// Compute xacc from ring slot SLOT (non-volatile loads; free to schedule
// within the current 8-step window).
#define XACC(SLOT) do {                                                        \
    const double2* xr = reinterpret_cast<const double2*>(&xring[(SLOT)][0]);   \
    const double2 q0 = xr[0], q1 = xr[1], q2 = xr[2];                          \
    const double  q3 = *reinterpret_cast<const double*>(&xring[(SLOT)][12]);   \
    const ull xp0 = d2l(q0.x), xp1 = d2l(q0.y), xp2 = d2l(q1.x),               \
              xp3 = d2l(q1.y), xp4 = d2l(q2.x), xp5 = d2l(q2.y),               \
              xp6 = d2l(q3);                                                   \
    xaA0 = fma2(xp0, wxA[0], biasPA);                                          \
    xaA1 = fma2(xp1, wxA[1], z64);                                             \
    xaA0 = fma2(xp2, wxA[2], xaA0);                                            \
    xaA1 = fma2(xp3, wxA[3], xaA1);                                            \
    xaA0 = fma2(xp4, wxA[4], xaA0);                                            \
    xaA1 = fma2(xp5, wxA[5], xaA1);                                            \
    xaA0 = fma2(xp6, wxA[6], xaA0);                                            \
    xaB0 = fma2(xp0, wxB[0], biasPB);                                          \
    xaB1 = fma2(xp1, wxB[1], z64);                                             \
    xaB0 = fma2(xp2, wxB[2], xaB0);                                            \
    xaB1 = fma2(xp3, wxB[3], xaB1);                                            \
    xaB0 = fma2(xp4, wxB[4], xaB0);                                            \
    xaB1 = fma2(xp5, wxB[5], xaB1);                                            \
    xaB0 = fma2(xp6, wxB[6], xaB0);                                            \
} while (0)

// One step: consume xacc (seeded with x-dot+bias), add h-dot, activate,
// ship f/o, update c/h, publish h; then (for XS >= 0) compute next xacc.
#define STEP(RB, WB, TTC, XS) do {                                             \
    ull hp[7];                                                                 \
    lds_h(hda + (RB) * 64, hp);                                                \
    ull cA0 = fma2(hp[0], whA[0], xaA0);                                       \
    ull cA1 = fma2(hp[1], whA[1], xaA1);                                       \
    cA0 = fma2(hp[2], whA[2], cA0);                                            \
    cA1 = fma2(hp[3], whA[3], cA1);                                            \
    cA0 = fma2(hp[4], whA[4], cA0);                                            \
    cA1 = fma2(hp[5], whA[5], cA1);                                            \
    cA0 = fma2(hp[6], whA[6], cA0);                                            \
    ull cB0 = fma2(hp[0], whB[0], xaB0);                                       \
    ull cB1 = fma2(hp[1], whB[1], xaB1);                                       \
    cB0 = fma2(hp[2], whB[2], cB0);                                            \
    cB1 = fma2(hp[3], whB[3], cB1);                                            \
    cB0 = fma2(hp[4], whB[4], cB0);                                            \
    cB1 = fma2(hp[5], whB[5], cB1);                                            \
    cB0 = fma2(hp[6], whB[6], cB0);                                            \
    const ull sA = add2(cA0, cA1);                                             \
    const ull sB = add2(cB0, cB1);                                             \
    float sa0, sa1, sb0, sb1;                                                  \
    upk(sA, sa0, sa1); upk(sB, sb0, sb1);                                      \
    const float preA = sa0 + sa1;                                              \
    const float preB = sb0 + sb1;                                              \
    const float actA = fmaf(0.5f, tanhap(preA), 0.5f);                         \
    const float actB = fmaf(mB,   tanhap(preB), aB);                           \
    if (lane == 26 && (TTC) > 0) ob[(TTC) - 1] = actB;                         \
    const float fg = __shfl_sync(FULLM, actA, (lane + 13) & 31);               \
    const float og = __shfl_sync(FULLM, actB, (lane + 13) & 31);               \
    c = fmaf(fg, c, actA * actB);                                              \
    h = og * tanhap(c);                                                        \
    if (lane < 13) sts_h(hda + (WB) * 64 + lane * 4, h);                       \
    if ((XS) >= 0) XACC(XS);   /* next step's x-dot fills the tail window */   \
} while (0)

    // Prologue: stage rows 0..7 as one commit group.
    #pragma unroll
    for (int r = 0; r < 8; r++)
        if (lane < 13) cp_async4(&xring[r][lane], xb + r * 13 + lane);
    cp_commit();

    for (int t = 0; t < TT; t += 16) {
        // Half 0: issue rows t+8..t+15 (slots 8..15); process slots 0..7.
        #pragma unroll
        for (int r = 0; r < 8; r++)
            if (lane < 13 && t + 8 + r < TT)
                cp_async4(&xring[8 + r][lane], xb + (size_t)(t + 8 + r) * 13 + lane);
        cp_commit();
        cp_wait1();          // rows t..t+7 resident
        __syncwarp();
        XACC(0);             // seed for step t (slot guaranteed by this wait)
        STEP(1, 0, t + 0, 1);
        STEP(0, 1, t + 1, 2);
        STEP(1, 0, t + 2, 3);
        STEP(0, 1, t + 3, 4);
        STEP(1, 0, t + 4, 5);
        STEP(0, 1, t + 5, 6);
        STEP(1, 0, t + 6, 7);
        STEP(0, 1, t + 7, -1);   // slot 8 not guaranteed yet; defer

        // Half 1: issue rows t+16..t+23 (slots 0..7); process slots 8..15.
        #pragma unroll
        for (int r = 0; r < 8; r++)
            if (lane < 13 && t + 16 + r < TT)
                cp_async4(&xring[r][lane], xb + (size_t)(t + 16 + r) * 13 + lane);
        cp_commit();
        cp_wait1();          // rows t+8..t+15 resident
        __syncwarp();
        XACC(8);
        STEP(1, 0, t +  8,  9);
        STEP(0, 1, t +  9, 10);
        STEP(1, 0, t + 10, 11);
        STEP(0, 1, t + 11, 12);
        STEP(1, 0, t + 12, 13);
        STEP(0, 1, t + 13, 14);
        STEP(1, 0, t + 14, 15);
        STEP(0, 1, t + 15, -1);
    }
#undef STEP
#undef XACC

    // Tail: ob[TT-1] = sigm(fc(h_{TT-1})); step 2047 wrote hbuf[1].
    __syncwarp();
    {
        float hk[13];
        #pragma unroll
        for (int k = 0; k < 13; k++) hk[k] = hbuf[1][k];
        float s0 = biasB, s1 = 0.0f, s2 = 0.0f, s3 = 0.0f;
        #pragma unroll
        for (int k = 0; k < 13; k++) {
            switch (k & 3) {
                case 0: s0 = fmaf(hk[k], whBs[k], s0); break;
                case 1: s1 = fmaf(hk[k], whBs[k], s1); break;
                case 2: s2 = fmaf(hk[k], whBs[k], s2); break;
                case 3: s3 = fmaf(hk[k], whBs[k], s3); break;
            }
        }
        const float pre  = (s0 + s1) + (s2 + s3);
        const float outv = fmaf(0.5f, tanhap(pre), 0.5f);
        if (lane == 26) ob[TT - 1] = outv;
    }
}

extern "C" void kernel_launch(void* const* d_in, const int* in_sizes, int n_in,
                              void* d_out, int out_size) {
    (void)in_sizes; (void)n_in; (void)out_size;
    const float* x    = (const float*)d_in[0];
    const float* W_ih = (const float*)d_in[1];
    const float* W_hh = (const float*)d_in[2];
    const float* b_ih = (const float*)d_in[3];
    const float* b_hh = (const float*)d_in[4];
    const float* fc_w = (const float*)d_in[5];
    const float* fc_b = (const float*)d_in[6];
    float* out = (float*)d_out;

    lstm_pipe<<<NB, 32>>>(x, W_ih, W_hh, b_ih, b_hh, fc_w, fc_b, out);
}

// round 13
// speedup vs baseline: 2.1973x; 1.1841x over previous
#include <cuda_runtime.h>

#define TT 2048
#define NB 512
#define FULLM 0xFFFFFFFFu
typedef unsigned long long ull;

__device__ __forceinline__ float tanhap(float x) {
    float r; asm("tanh.approx.f32 %0, %1;" : "=f"(r) : "f"(x)); return r;
}
__device__ __forceinline__ ull pk(float lo, float hi) {
    ull r; asm("mov.b64 %0, {%1, %2};" : "=l"(r) : "f"(lo), "f"(hi)); return r;
}
__device__ __forceinline__ void upk(ull v, float& lo, float& hi) {
    asm("mov.b64 {%0, %1}, %2;" : "=f"(lo), "=f"(hi) : "l"(v));
}
__device__ __forceinline__ ull fma2(ull a, ull b, ull c) {
    ull d; asm("fma.rn.f32x2 %0, %1, %2, %3;" : "=l"(d) : "l"(a), "l"(b), "l"(c)); return d;
}
__device__ __forceinline__ ull add2(ull a, ull b) {
    ull d; asm("add.rn.f32x2 %0, %1, %2;" : "=l"(d) : "l"(a), "l"(b)); return d;
}
__device__ __forceinline__ ull d2l(double d) { return (ull)__double_as_longlong(d); }

__device__ __forceinline__ void cp_async4(void* smem_dst, const void* gmem_src) {
    unsigned saddr = (unsigned)__cvta_generic_to_shared(smem_dst);
    asm volatile("cp.async.ca.shared.global [%0], [%1], 4;\n"
                 :: "r"(saddr), "l"(gmem_src) : "memory");
}
__device__ __forceinline__ void cp_commit() {
    asm volatile("cp.async.commit_group;\n" ::: "memory");
}
__device__ __forceinline__ void cp_wait4() {
    asm volatile("cp.async.wait_group 4;\n" ::: "memory");
}

// 4-chain packed dot: x terms first (register-resident early), h terms last
// (depth <=2 from h arrival), then add2 tree.
__device__ __forceinline__ float dotg(const ull* xp, const ull* hp,
                                      const ull* wx, const ull* wh,
                                      ull bias, ull z) {
    ull c0 = fma2(xp[0], wx[0], bias);
    ull c1 = fma2(xp[1], wx[1], z);
    ull c2 = fma2(xp[2], wx[2], z);
    ull c3 = fma2(xp[3], wx[3], z);
    c0 = fma2(xp[4], wx[4], c0);
    c1 = fma2(xp[5], wx[5], c1);
    c2 = fma2(xp[6], wx[6], c2);
    c3 = fma2(hp[0], wh[0], c3);
    c0 = fma2(hp[1], wh[1], c0);
    c1 = fma2(hp[2], wh[2], c1);
    c2 = fma2(hp[3], wh[3], c2);
    c3 = fma2(hp[4], wh[4], c3);
    c0 = fma2(hp[5], wh[5], c0);
    c1 = fma2(hp[6], wh[6], c1);
    ull s = add2(add2(c0, c1), add2(c2, c3));
    float lo, hi; upk(s, lo, hi);
    return lo + hi;
}

__device__ __forceinline__ void ldpairs(const float* row, ull* p) {
    const double2* r = reinterpret_cast<const double2*>(row);
    const double2 q0 = r[0], q1 = r[1], q2 = r[2];
    const double  q3 = *reinterpret_cast<const double*>(row + 12);
    p[0] = d2l(q0.x); p[1] = d2l(q0.y); p[2] = d2l(q1.x); p[3] = d2l(q1.y);
    p[4] = d2l(q2.x); p[5] = d2l(q2.y); p[6] = d2l(q3);
}

__global__ void __launch_bounds__(32)
lstm_nobranch(const float* __restrict__ x,
              const float* __restrict__ W_ih,
              const float* __restrict__ W_hh,
              const float* __restrict__ b_ih,
              const float* __restrict__ b_hh,
              const float* __restrict__ fc_w,
              const float* __restrict__ fc_b,
              float* __restrict__ out)
{
    // 32-wide rows: every lane writes its own slot -> no predication anywhere.
    // Elements 13..31 are pads consumed only via 0-packed weights.
    __shared__ __align__(16) float xring[8][32];
    __shared__ __align__(16) float hbuf[2][32];

    const int lane = threadIdx.x & 31;
    const int seq  = blockIdx.x;
    const float* xb = x + (size_t)seq * TT * 13;
    float* ob = out + (size_t)seq * TT;

    // Clamped x element: lanes >=13 redundantly fetch element 12 into pads.
    const int kcl = (lane < 13) ? lane : 12;

    hbuf[0][lane] = 0.0f;
    hbuf[1][lane] = 0.0f;

    // Lane L<26: A = gate L (sigmoid: i for L<13, f else), B = gate 26+L
    // (g=tanh for L<13, o=sigmoid else). Lane 26: B-dot = FC head.
    // Sigmoid pre-scale 0.5 folded into weights: act = m*tanh(pre)+a.
    float wiA[13], whAs[13], wiB[13], whBs[13];
    float biasA = 0.0f, biasB = 0.0f;
    {
        const bool g26 = (lane < 26);
        const float sA = 0.5f;
        const float sB = (lane < 13) ? 1.0f : 0.5f;
        const int rA = g26 ? lane : 0;
        const int rB = g26 ? lane + 26 : 0;
        #pragma unroll
        for (int k = 0; k < 13; k++) {
            wiA[k]  = g26 ? sA * W_ih[rA * 13 + k] : 0.0f;
            whAs[k] = g26 ? sA * W_hh[rA * 13 + k] : 0.0f;
            wiB[k]  = g26 ? sB * W_ih[rB * 13 + k] : 0.0f;
            whBs[k] = g26 ? sB * W_hh[rB * 13 + k] : 0.0f;
        }
        if (g26) {
            biasA = sA * (b_ih[rA] + b_hh[rA]);
            biasB = sB * (b_ih[rB] + b_hh[rB]);
        }
        if (lane == 26) {
            #pragma unroll
            for (int k = 0; k < 13; k++) { wiB[k] = 0.0f; whBs[k] = 0.5f * fc_w[k]; }
            biasB = 0.5f * fc_b[0];
        }
    }

    ull wxA[7], whA[7], wxB[7], whB[7];
    #pragma unroll
    for (int p = 0; p < 6; p++) {
        wxA[p] = pk(wiA[2*p],  wiA[2*p+1]);
        whA[p] = pk(whAs[2*p], whAs[2*p+1]);
        wxB[p] = pk(wiB[2*p],  wiB[2*p+1]);
        whB[p] = pk(whBs[2*p], whBs[2*p+1]);
    }
    wxA[6] = pk(wiA[12],  0.0f);   // hi halves hit pad element 13 -> x*0
    whA[6] = pk(whAs[12], 0.0f);
    wxB[6] = pk(wiB[12],  0.0f);
    whB[6] = pk(whBs[12], 0.0f);

    const ull biasPA = pk(biasA, 0.0f);
    const ull biasPB = pk(biasB, 0.0f);
    const ull zero64 = pk(0.0f, 0.0f);

    const float mB = (lane < 13) ? 1.0f : 0.5f;
    const float aB = (lane < 13) ? 0.0f : 0.5f;

    float h = 0.0f, c = 0.0f;

    // Prologue: stage x rows 0..4 (5 commit groups), then row 0 to regs.
    #pragma unroll
    for (int t0 = 0; t0 < 5; t0++) {
        cp_async4(&xring[t0][lane], xb + t0 * 13 + kcl);   // all 32 lanes
        cp_commit();
    }
    cp_wait4();
    __syncwarp();
    ull xcur[7];
    ldpairs(&xring[0][0], xcur);

    for (int t = 0; t < TT; t += 8) {
        #pragma unroll
        for (int u = 0; u < 8; u++) {
            const int tt    = t + u;
            const int wslot = (u + 5) & 7;
            const int nslot = (u + 1) & 7;
            const int hbr   = (u + 1) & 1;
            const int hbw   = u & 1;

            // Unconditional fetch of row tt+5 (row clamped near the end).
            int rowc = tt + 5;
            rowc = (rowc > TT - 1) ? (TT - 1) : rowc;
            cp_async4(&xring[wslot][lane], xb + (size_t)rowc * 13 + kcl);
            cp_commit();
            cp_wait4();          // row tt+1 resident
            __syncwarp();        // cp visibility + prev STS h visibility

            ull hp[7];
            ldpairs(&hbuf[hbr][0], hp);
            ull xnxt[7];
            ldpairs(&xring[nslot][0], xnxt);

            const float preA = dotg(xcur, hp, wxA, whA, biasPA, zero64);
            const float preB = dotg(xcur, hp, wxB, whB, biasPB, zero64);

            const float actA = fmaf(0.5f, tanhap(preA), 0.5f);   // sigm i/f
            const float actB = fmaf(mB,   tanhap(preB), aB);     // g / o / FC

            // Lane 26's actB == sigm(fc(h_{tt-1})). Step 0 writes garbage to
            // ob[0]; step 1 overwrites it (same thread, program order).
            int ttm = tt - 1;
            ttm = (ttm < 0) ? 0 : ttm;
            if (lane == 26) ob[ttm] = actB;    // single predicated STG

            const float fg = __shfl_sync(FULLM, actA, (lane + 13) & 31);
            const float og = __shfl_sync(FULLM, actB, (lane + 13) & 31);

            c = fmaf(fg, c, actA * actB);
            h = og * tanhap(c);
            hbuf[hbw][lane] = h;               // all 32 lanes; pads harmless

            #pragma unroll
            for (int p = 0; p < 7; p++) xcur[p] = xnxt[p];
        }
    }

    // Tail: ob[TT-1] = sigm(fc(h_{TT-1})); step 2047 wrote hbuf[1].
    __syncwarp();
    {
        float hk[13];
        #pragma unroll
        for (int k = 0; k < 13; k++) hk[k] = hbuf[1][k];
        float s0 = biasB, s1 = 0.0f, s2 = 0.0f, s3 = 0.0f;
        #pragma unroll
        for (int k = 0; k < 13; k++) {
            switch (k & 3) {
                case 0: s0 = fmaf(hk[k], whBs[k], s0); break;
                case 1: s1 = fmaf(hk[k], whBs[k], s1); break;
                case 2: s2 = fmaf(hk[k], whBs[k], s2); break;
                case 3: s3 = fmaf(hk[k], whBs[k], s3); break;
            }
        }
        const float pre  = (s0 + s1) + (s2 + s3);
        const float outv = fmaf(0.5f, tanhap(pre), 0.5f);
        if (lane == 26) ob[TT - 1] = outv;
    }
}

extern "C" void kernel_launch(void* const* d_in, const int* in_sizes, int n_in,
                              void* d_out, int out_size) {
    (void)in_sizes; (void)n_in; (void)out_size;
    const float* x    = (const float*)d_in[0];
    const float* W_ih = (const float*)d_in[1];
    const float* W_hh = (const float*)d_in[2];
    const float* b_ih = (const float*)d_in[3];
    const float* b_hh = (const float*)d_in[4];
    const float* fc_w = (const float*)d_in[5];
    const float* fc_b = (const float*)d_in[6];
    float* out = (float*)d_out;

    lstm_nobranch<<<NB, 32>>>(x, W_ih, W_hh, b_ih, b_hh, fc_w, fc_b, out);
}